// round 13
// baseline (speedup 1.0000x reference)
#include <cuda_runtime.h>
#include <cstddef>

using ull = unsigned long long;

// Problem constants (fixed by the dataset)
constexpr int Bc  = 4;
constexpr int Tc  = 2048;
constexpr int Dc  = 512;
constexpr int Hc  = 8;
constexpr int DKc = 64;   // Dc / Hc

// -------------------- scratch (device globals; no allocation allowed) ------
__device__ float g_Q[(size_t)Bc * Tc * Dc];
__device__ float g_K[(size_t)Bc * Tc * Dc];   // K proj, then Kp = K + P in-place
__device__ float g_V[(size_t)Bc * Tc * Dc];
__device__ float g_P[(size_t)Tc * Dc];
__device__ float g_C[(size_t)Bc * Hc * Tc];   // per-(b,h,s) bias  u.k + v.p
__device__ float g_X[(size_t)Bc * Tc * Dc];

// -------------------- packed f32x2 helpers (sm_103a FFMA2) -----------------
__device__ __forceinline__ ull pack2(float x, float y) {
    ull r; asm("mov.b64 %0, {%1, %2};" : "=l"(r) : "f"(x), "f"(y)); return r;
}
__device__ __forceinline__ float2 unpack2(ull v) {
    float2 f; asm("mov.b64 {%0, %1}, %2;" : "=f"(f.x), "=f"(f.y) : "l"(v)); return f;
}
__device__ __forceinline__ void ffma2(ull& d, ull a, ull b) {
    asm("fma.rn.f32x2 %0, %1, %2, %0;" : "+l"(d) : "l"(a), "l"(b));
}
__device__ __forceinline__ ull fmul2(ull a, ull b) {
    ull r; asm("mul.rn.f32x2 %0, %1, %2;" : "=l"(r) : "l"(a), "l"(b)); return r;
}

// ---------------------------------------------------------------------------
// GEMM: out[M,N] = A[M,K] @ W[N,K]^T (+ bias[N]).
// Tile 128x128x16, 256 threads, 8x8 microtile, packed f32x2 FMA.
// A tile stored DUPLICATED in smem ({a,a} per value) so the broadcast operand
// is read directly as packed dup-pairs; W tile packed pairs read natively.
// ---------------------------------------------------------------------------
__global__ __launch_bounds__(256, 2) void gemm_bias_kernel(
    const float* __restrict__ A, const float* __restrict__ W,
    const float* __restrict__ bias, float* __restrict__ out,
    int M, int N, int K)
{
    __shared__ float As[16 * 264];   // [k][2*m], ull-stride 132 (128 pairs + 4 pad)
    __shared__ float Ws[16 * 136];   // [k][n],   ull-stride 68

    const int tid = threadIdx.x;
    const int tx = tid & 15, ty = tid >> 4;
    const int m0 = blockIdx.y << 7, n0 = blockIdx.x << 7;
    const int lr = tid >> 1;            // 0..127  (row within tile)
    const int lc = (tid & 1) << 3;      // 0 or 8  (k offset within tile)

    const float* Ap = A + (size_t)(m0 + lr) * K + lc;
    const float* Wp = W + (size_t)(n0 + lr) * K + lc;
    ull* AsU = (ull*)As;

    ull acc[8][4];
#pragma unroll
    for (int i = 0; i < 8; i++)
#pragma unroll
        for (int j = 0; j < 4; j++) acc[i][j] = 0ull;

    for (int k0 = 0; k0 < K; k0 += 16) {
        float4 a0 = *(const float4*)(Ap + k0);
        float4 a1 = *(const float4*)(Ap + k0 + 4);
        float4 w0 = *(const float4*)(Wp + k0);
        float4 w1 = *(const float4*)(Wp + k0 + 4);
        __syncthreads();            // previous compute done before overwrite
        AsU[(lc + 0) * 132 + lr] = pack2(a0.x, a0.x);
        AsU[(lc + 1) * 132 + lr] = pack2(a0.y, a0.y);
        AsU[(lc + 2) * 132 + lr] = pack2(a0.z, a0.z);
        AsU[(lc + 3) * 132 + lr] = pack2(a0.w, a0.w);
        AsU[(lc + 4) * 132 + lr] = pack2(a1.x, a1.x);
        AsU[(lc + 5) * 132 + lr] = pack2(a1.y, a1.y);
        AsU[(lc + 6) * 132 + lr] = pack2(a1.z, a1.z);
        AsU[(lc + 7) * 132 + lr] = pack2(a1.w, a1.w);
        Ws[(lc + 0) * 136 + lr] = w0.x;
        Ws[(lc + 1) * 136 + lr] = w0.y;
        Ws[(lc + 2) * 136 + lr] = w0.z;
        Ws[(lc + 3) * 136 + lr] = w0.w;
        Ws[(lc + 4) * 136 + lr] = w1.x;
        Ws[(lc + 5) * 136 + lr] = w1.y;
        Ws[(lc + 6) * 136 + lr] = w1.z;
        Ws[(lc + 7) * 136 + lr] = w1.w;
        __syncthreads();

        const ull* Au = (const ull*)As;
        const ull* Wu = (const ull*)Ws;
#pragma unroll
        for (int k = 0; k < 16; k++) {
            const ull* ap = Au + k * 132 + (ty << 3);
            const ull* bp = Wu + k * 68 + (tx << 2);
            ulonglong2 av0 = *(const ulonglong2*)(ap + 0);
            ulonglong2 av1 = *(const ulonglong2*)(ap + 2);
            ulonglong2 av2 = *(const ulonglong2*)(ap + 4);
            ulonglong2 av3 = *(const ulonglong2*)(ap + 6);
            ulonglong2 bv0 = *(const ulonglong2*)(bp + 0);
            ulonglong2 bv1 = *(const ulonglong2*)(bp + 2);
            ull ad[8] = {av0.x, av0.y, av1.x, av1.y, av2.x, av2.y, av3.x, av3.y};
            ull bd[4] = {bv0.x, bv0.y, bv1.x, bv1.y};
#pragma unroll
            for (int i = 0; i < 8; i++)
#pragma unroll
                for (int j = 0; j < 4; j++)
                    ffma2(acc[i][j], ad[i], bd[j]);
        }
    }

#pragma unroll
    for (int i = 0; i < 8; i++) {
        const int m = m0 + (ty << 3) + i;
        float* op = out + (size_t)m * N + n0 + (tx << 3);
#pragma unroll
        for (int jp = 0; jp < 4; jp++) {
            float2 f = unpack2(acc[i][jp]);
            const int nn = n0 + (tx << 3) + 2 * jp;
            float b0 = bias ? bias[nn]     : 0.f;
            float b1 = bias ? bias[nn + 1] : 0.f;
            ((float2*)op)[jp] = make_float2(f.x + b0, f.y + b1);
        }
    }
}

// ---------------------------------------------------------------------------
// Fuse: Kp = K + P (in place), C[b,h,s] = sum_d u[h,d]*K + v[h,d]*P
// ---------------------------------------------------------------------------
__global__ __launch_bounds__(512) void kp_c_kernel(
    float* __restrict__ K, const float* __restrict__ P,
    const float* __restrict__ u, const float* __restrict__ v,
    float* __restrict__ C)
{
    __shared__ float prod[512];
    const int bs = blockIdx.x;
    const int s  = bs & (Tc - 1);
    const int d  = threadIdx.x;

    const size_t kidx = (size_t)bs * Dc + d;
    float kv = K[kidx];
    float pv = P[(size_t)s * Dc + d];
    K[kidx] = kv + pv;
    prod[d] = u[d] * kv + v[d] * pv;
    __syncthreads();
#pragma unroll
    for (int off = 32; off > 0; off >>= 1) {
        if ((d & 63) < off) prod[d] += prod[d + off];
        __syncthreads();
    }
    if ((d & 63) == 0) {
        const int b = bs >> 11;
        C[((size_t)b * Hc + (d >> 6)) * Tc + s] = prod[d];
    }
}

// ---------------------------------------------------------------------------
// Flash attention (fp32, packed f32x2 FMA). Block = (b, h, 64-query tile),
// 256 threads, 4x4 microtile. Q and P tiles duplicated in smem so the
// broadcast operand reads as packed dup-pairs.
// ---------------------------------------------------------------------------
// smem layout (floats):
//  Qs  [d=64][2*tq=128 + 8 pad]   stride 136  (ull stride 68)   8704
//  Ks  [d=64][ts=64 + 4 pad]      stride 68   (ull stride 34)   4352
//  Ps  [ts=64][2*tq=128 + 4 pad]  stride 132  (ull stride 66)   8448
//  Vs  [ts=64][dv=64]             stride 64   (ull stride 32)   4096
//  Cs[64], Ms[64]
constexpr int OFF_QS = 0;
constexpr int OFF_KS = OFF_QS + 64 * 136;
constexpr int OFF_PS = OFF_KS + 64 * 68;
constexpr int OFF_VS = OFF_PS + 64 * 132;
constexpr int OFF_CS = OFF_VS + 64 * 64;
constexpr int OFF_MS = OFF_CS + 64;
constexpr int ATTN_SMEM_FLOATS = OFF_MS + 64;
constexpr int ATTN_SMEM_BYTES  = ATTN_SMEM_FLOATS * 4;   // 102912

__global__ __launch_bounds__(256, 2) void attn_kernel(
    const float* __restrict__ Q, const float* __restrict__ Kp,
    const float* __restrict__ V, const float* __restrict__ C,
    const int* __restrict__ mask, float* __restrict__ X)
{
    extern __shared__ float sm[];
    float* Qs = sm + OFF_QS;
    float* Ks = sm + OFF_KS;
    float* Ps = sm + OFF_PS;
    float* Vs = sm + OFF_VS;
    float* Cs = sm + OFF_CS;
    float* Ms = sm + OFF_MS;
    ull* QsU = (ull*)Qs;
    ull* PsU = (ull*)Ps;

    const int tid = threadIdx.x;
    const int tx = tid & 15, ty = tid >> 4;
    const int b = blockIdx.z, h = blockIdx.y;
    const int t0 = blockIdx.x << 6;
    const int lr = tid >> 2, lcg = tid & 3;

    // Load Q tile transposed + duplicated into smem
    {
        const float* qb = Q + ((size_t)(b * Tc + t0 + lr)) * Dc + h * DKc;
#pragma unroll
        for (int c = 0; c < 4; c++) {
            const int dd = lcg * 16 + c * 4;
            float4 qv = *(const float4*)(qb + dd);
            QsU[(dd + 0) * 68 + lr] = pack2(qv.x, qv.x);
            QsU[(dd + 1) * 68 + lr] = pack2(qv.y, qv.y);
            QsU[(dd + 2) * 68 + lr] = pack2(qv.z, qv.z);
            QsU[(dd + 3) * 68 + lr] = pack2(qv.w, qv.w);
        }
    }

    float m_i[4], l_i[4];
    ull oacc[4][2];
#pragma unroll
    for (int i = 0; i < 4; i++) {
        m_i[i] = -1e30f; l_i[i] = 0.f;
        oacc[i][0] = 0ull; oacc[i][1] = 0ull;
    }

    for (int s0 = 0; s0 < Tc; s0 += 64) {
        // Load K (transposed), V (natural), C, mask for this s-tile
        {
            const float* kb = Kp + ((size_t)(b * Tc + s0 + lr)) * Dc + h * DKc;
            const float* vb = V  + ((size_t)(b * Tc + s0 + lr)) * Dc + h * DKc;
#pragma unroll
            for (int c = 0; c < 4; c++) {
                const int dd = lcg * 16 + c * 4;
                float4 kv = *(const float4*)(kb + dd);
                Ks[(dd + 0) * 68 + lr] = kv.x;
                Ks[(dd + 1) * 68 + lr] = kv.y;
                Ks[(dd + 2) * 68 + lr] = kv.z;
                Ks[(dd + 3) * 68 + lr] = kv.w;
                float4 vv = *(const float4*)(vb + dd);
                *(float4*)&Vs[lr * 64 + dd] = vv;
            }
            if (tid < 64) {
                Cs[tid] = C[((size_t)b * Hc + h) * Tc + s0 + tid];
                Ms[tid] = (float)mask[b * Tc + s0 + tid];
            }
        }
        __syncthreads();   // tiles ready (covers Q stores on first iter)

        // S = Q . Kp^T : sacc packed over j (key pairs)
        ull sacc[4][2];
#pragma unroll
        for (int i = 0; i < 4; i++) { sacc[i][0] = 0ull; sacc[i][1] = 0ull; }

        {
            const ull* Qu = (const ull*)Qs;
            const ull* Ku = (const ull*)Ks;
#pragma unroll 8
            for (int d = 0; d < 64; d++) {
                const ull* qp = Qu + d * 68 + (ty << 2);
                ulonglong2 qa0 = *(const ulonglong2*)(qp + 0);
                ulonglong2 qa1 = *(const ulonglong2*)(qp + 2);
                ulonglong2 kb2 = *(const ulonglong2*)(Ku + d * 34 + (tx << 1));
                ffma2(sacc[0][0], qa0.x, kb2.x); ffma2(sacc[0][1], qa0.x, kb2.y);
                ffma2(sacc[1][0], qa0.y, kb2.x); ffma2(sacc[1][1], qa0.y, kb2.y);
                ffma2(sacc[2][0], qa1.x, kb2.x); ffma2(sacc[2][1], qa1.x, kb2.y);
                ffma2(sacc[3][0], qa1.y, kb2.x); ffma2(sacc[3][1], qa1.y, kb2.y);
            }
        }

        // Online softmax
        float cj[4], mk[4];
#pragma unroll
        for (int j = 0; j < 4; j++) {
            cj[j] = Cs[(tx << 2) + j];
            mk[j] = Ms[(tx << 2) + j];
        }
#pragma unroll
        for (int i = 0; i < 4; i++) {
            float2 s01 = unpack2(sacc[i][0]);
            float2 s23 = unpack2(sacc[i][1]);
            float sv[4] = {s01.x, s01.y, s23.x, s23.y};
#pragma unroll
            for (int j = 0; j < 4; j++)
                sv[j] = (mk[j] != 0.f) ? (sv[j] + cj[j]) * 0.125f : -1e30f;
            float tmax = fmaxf(fmaxf(sv[0], sv[1]), fmaxf(sv[2], sv[3]));
#pragma unroll
            for (int off = 8; off > 0; off >>= 1)
                tmax = fmaxf(tmax, __shfl_xor_sync(0xffffffffu, tmax, off));
            float mnew  = fmaxf(m_i[i], tmax);
            float alpha = __expf(m_i[i] - mnew);
            m_i[i] = mnew;
            float rs = 0.f;
#pragma unroll
            for (int j = 0; j < 4; j++) {
                float p = (mk[j] != 0.f) ? __expf(sv[j] - mnew) : 0.f;
                rs += p;
                PsU[((tx << 2) + j) * 66 + (ty << 2) + i] = pack2(p, p);
            }
#pragma unroll
            for (int off = 8; off > 0; off >>= 1)
                rs += __shfl_xor_sync(0xffffffffu, rs, off);
            l_i[i] = l_i[i] * alpha + rs;
            ull al2 = pack2(alpha, alpha);
            oacc[i][0] = fmul2(oacc[i][0], al2);
            oacc[i][1] = fmul2(oacc[i][1], al2);
        }
        __syncthreads();   // Ps visible to all

        // O += P @ V : packed over j (dv pairs), dup-pairs of P read direct
        {
            const ull* Pu = (const ull*)Ps;
            const ull* Vu = (const ull*)Vs;
#pragma unroll 8
            for (int ts = 0; ts < 64; ts++) {
                const ull* pp = Pu + ts * 66 + (ty << 2);
                ulonglong2 pa0 = *(const ulonglong2*)(pp + 0);
                ulonglong2 pa1 = *(const ulonglong2*)(pp + 2);
                ulonglong2 vb2 = *(const ulonglong2*)(Vu + ts * 32 + (tx << 1));
                ffma2(oacc[0][0], pa0.x, vb2.x); ffma2(oacc[0][1], pa0.x, vb2.y);
                ffma2(oacc[1][0], pa0.y, vb2.x); ffma2(oacc[1][1], pa0.y, vb2.y);
                ffma2(oacc[2][0], pa1.x, vb2.x); ffma2(oacc[2][1], pa1.x, vb2.y);
                ffma2(oacc[3][0], pa1.y, vb2.x); ffma2(oacc[3][1], pa1.y, vb2.y);
            }
        }
        __syncthreads();   // done with tiles before next iteration overwrites
    }

    // Normalize and write X
#pragma unroll
    for (int i = 0; i < 4; i++) {
        float inv = (l_i[i] > 0.f) ? (1.f / l_i[i]) : 0.f;
        float* xp = X + ((size_t)(b * Tc + t0 + (ty << 2) + i)) * Dc
                      + h * DKc + (tx << 2);
        float2 f0 = unpack2(oacc[i][0]);
        float2 f1 = unpack2(oacc[i][1]);
        ((float2*)xp)[0] = make_float2(f0.x * inv, f0.y * inv);
        ((float2*)xp)[1] = make_float2(f1.x * inv, f1.y * inv);
    }
}

// ---------------------------------------------------------------------------
extern "C" void kernel_launch(void* const* d_in, const int* in_sizes, int n_in,
                              void* d_out, int out_size)
{
    (void)in_sizes; (void)n_in; (void)out_size;
    const float* query = (const float*)d_in[0];
    const float* key   = (const float*)d_in[1];
    const float* value = (const float*)d_in[2];
    const int*   mask  = (const int*)  d_in[3];
    const float* pos   = (const float*)d_in[4];
    const float* Wq    = (const float*)d_in[5];
    const float* bq    = (const float*)d_in[6];
    const float* Wk    = (const float*)d_in[7];
    const float* bk    = (const float*)d_in[8];
    const float* Wv    = (const float*)d_in[9];
    const float* bv    = (const float*)d_in[10];
    const float* Wo    = (const float*)d_in[11];
    const float* bo    = (const float*)d_in[12];
    const float* Wp    = (const float*)d_in[13];
    const float* u     = (const float*)d_in[14];
    const float* v     = (const float*)d_in[15];
    float* out = (float*)d_out;

    float *Qb, *Kb, *Vb, *Pb, *Cb, *Xb;
    cudaGetSymbolAddress((void**)&Qb, g_Q);
    cudaGetSymbolAddress((void**)&Kb, g_K);
    cudaGetSymbolAddress((void**)&Vb, g_V);
    cudaGetSymbolAddress((void**)&Pb, g_P);
    cudaGetSymbolAddress((void**)&Cb, g_C);
    cudaGetSymbolAddress((void**)&Xb, g_X);

    cudaFuncSetAttribute(attn_kernel,
                         cudaFuncAttributeMaxDynamicSharedMemorySize,
                         ATTN_SMEM_BYTES);

    // P = pos_emb @ Wp^T (no bias)
    gemm_bias_kernel<<<dim3(Dc / 128, Tc / 128), 256>>>(pos, Wp, nullptr, Pb, Tc, Dc, Dc);
    // Q/K/V projections
    gemm_bias_kernel<<<dim3(Dc / 128, (Bc * Tc) / 128), 256>>>(query, Wq, bq, Qb, Bc * Tc, Dc, Dc);
    gemm_bias_kernel<<<dim3(Dc / 128, (Bc * Tc) / 128), 256>>>(key,   Wk, bk, Kb, Bc * Tc, Dc, Dc);
    gemm_bias_kernel<<<dim3(Dc / 128, (Bc * Tc) / 128), 256>>>(value, Wv, bv, Vb, Bc * Tc, Dc, Dc);
    // Kp = K + P (in place) and per-(b,h,s) bias C = u.k + v.p
    kp_c_kernel<<<Bc * Tc, Dc>>>(Kb, Pb, u, v, Cb);
    // Flash attention
    attn_kernel<<<dim3(Tc / 64, Hc, Bc), 256, ATTN_SMEM_BYTES>>>(Qb, Kb, Vb, Cb, mask, Xb);
    // Output projection
    gemm_bias_kernel<<<dim3(Dc / 128, (Bc * Tc) / 128), 256>>>(Xb, Wo, bo, out, Bc * Tc, Dc, Dc);
}

// round 14
// speedup vs baseline: 2.3808x; 2.3808x over previous
#include <cuda_runtime.h>
#include <cstddef>

// Problem constants (fixed by the dataset)
constexpr int Bc  = 4;
constexpr int Tc  = 2048;
constexpr int Dc  = 512;
constexpr int Hc  = 8;
constexpr int DKc = 64;   // Dc / Hc

// -------------------- scratch (device globals; no allocation allowed) ------
__device__ float g_Q[(size_t)Bc * Tc * Dc];
__device__ float g_K[(size_t)Bc * Tc * Dc];   // K proj, then Kp = K + P in-place
__device__ float g_V[(size_t)Bc * Tc * Dc];
__device__ float g_P[(size_t)Tc * Dc];
__device__ float g_C[(size_t)Bc * Hc * Tc];   // per-(b,h,s) bias  u.k + v.p
__device__ float g_X[(size_t)Bc * Tc * Dc];

// -------------------- tf32 helpers -----------------------------------------
__device__ __forceinline__ unsigned cvt_tf32(float f) {
    unsigned r; asm("cvt.rna.tf32.f32 %0, %1;" : "=r"(r) : "f"(f)); return r;
}
__device__ __forceinline__ void mma_tf32(
    float& c0, float& c1, float& c2, float& c3,
    unsigned a0, unsigned a1, unsigned a2, unsigned a3,
    unsigned b0, unsigned b1)
{
    asm("mma.sync.aligned.m16n8k8.row.col.f32.tf32.tf32.f32 "
        "{%0,%1,%2,%3}, {%4,%5,%6,%7}, {%8,%9}, {%0,%1,%2,%3};"
        : "+f"(c0), "+f"(c1), "+f"(c2), "+f"(c3)
        : "r"(a0), "r"(a1), "r"(a2), "r"(a3), "r"(b0), "r"(b1));
}

// ---------------------------------------------------------------------------
// GEMM (exact fp32 SIMT, proven R11): out[M,N] = A[M,K] @ W[N,K]^T (+ bias).
// Tiles 64x64x16, 256 thr, 4x4 microtile.
// ---------------------------------------------------------------------------
__global__ __launch_bounds__(256) void gemm_bias_kernel(
    const float* __restrict__ A, const float* __restrict__ W,
    const float* __restrict__ bias, float* __restrict__ out,
    int M, int N, int K)
{
    __shared__ float As[16 * 68];
    __shared__ float Ws[16 * 68];

    const int tid = threadIdx.x;
    const int tx = tid & 15, ty = tid >> 4;
    const int m0 = blockIdx.y << 6, n0 = blockIdx.x << 6;
    const int lr = tid >> 2;
    const int lc = (tid & 3) << 2;

    const float* Ap = A + (size_t)(m0 + lr) * K + lc;
    const float* Wp = W + (size_t)(n0 + lr) * K + lc;

    float acc[4][4];
#pragma unroll
    for (int i = 0; i < 4; i++)
#pragma unroll
        for (int j = 0; j < 4; j++) acc[i][j] = 0.f;

    for (int k0 = 0; k0 < K; k0 += 16) {
        float4 av = *(const float4*)(Ap + k0);
        float4 wv = *(const float4*)(Wp + k0);
        __syncthreads();
        As[(lc + 0) * 68 + lr] = av.x;
        As[(lc + 1) * 68 + lr] = av.y;
        As[(lc + 2) * 68 + lr] = av.z;
        As[(lc + 3) * 68 + lr] = av.w;
        Ws[(lc + 0) * 68 + lr] = wv.x;
        Ws[(lc + 1) * 68 + lr] = wv.y;
        Ws[(lc + 2) * 68 + lr] = wv.z;
        Ws[(lc + 3) * 68 + lr] = wv.w;
        __syncthreads();
#pragma unroll
        for (int k = 0; k < 16; k++) {
            float4 a  = *(const float4*)&As[k * 68 + (ty << 2)];
            float4 bb = *(const float4*)&Ws[k * 68 + (tx << 2)];
            float ar[4] = {a.x, a.y, a.z, a.w};
            float br[4] = {bb.x, bb.y, bb.z, bb.w};
#pragma unroll
            for (int i = 0; i < 4; i++)
#pragma unroll
                for (int j = 0; j < 4; j++)
                    acc[i][j] = fmaf(ar[i], br[j], acc[i][j]);
        }
    }

#pragma unroll
    for (int i = 0; i < 4; i++) {
        const int m = m0 + (ty << 2) + i;
        float* op = out + (size_t)m * N + n0 + (tx << 2);
#pragma unroll
        for (int j = 0; j < 4; j++) {
            float bv = bias ? bias[n0 + (tx << 2) + j] : 0.f;
            op[j] = acc[i][j] + bv;
        }
    }
}

// ---------------------------------------------------------------------------
// Fuse: Kp = K + P (in place), C[b,h,s] = sum_d u[h,d]*K + v[h,d]*P
// ---------------------------------------------------------------------------
__global__ __launch_bounds__(512) void kp_c_kernel(
    float* __restrict__ K, const float* __restrict__ P,
    const float* __restrict__ u, const float* __restrict__ v,
    float* __restrict__ C)
{
    __shared__ float prod[512];
    const int bs = blockIdx.x;
    const int s  = bs & (Tc - 1);
    const int d  = threadIdx.x;

    const size_t kidx = (size_t)bs * Dc + d;
    float kv = K[kidx];
    float pv = P[(size_t)s * Dc + d];
    K[kidx] = kv + pv;
    prod[d] = u[d] * kv + v[d] * pv;
    __syncthreads();
#pragma unroll
    for (int off = 32; off > 0; off >>= 1) {
        if ((d & 63) < off) prod[d] += prod[d + off];
        __syncthreads();
    }
    if ((d & 63) == 0) {
        const int b = bs >> 11;
        C[((size_t)b * Hc + (d >> 6)) * Tc + s] = prod[d];
    }
}

// ---------------------------------------------------------------------------
// Flash attention with mma.sync m16n8k8 TF32.
// Block = (b, h, 64-query tile), 128 threads (4 warps x 16 queries).
// smem (unsigned / float words):
//   Ks [64][68]  (tf32 K tile; also reused for Q preload)
//   Vs [64][72]  (tf32 V tile)
//   Ps [64][68]  (tf32 P probs)
//   Cs [64], Ms [64]
// ---------------------------------------------------------------------------
constexpr int ATTN_SMEM_WORDS = 64 * 68 + 64 * 72 + 64 * 68 + 64 + 64;
constexpr int ATTN_SMEM_BYTES = ATTN_SMEM_WORDS * 4;   // 53760

__global__ __launch_bounds__(128) void attn_kernel(
    const float* __restrict__ Q, const float* __restrict__ Kp,
    const float* __restrict__ V, const float* __restrict__ C,
    const int* __restrict__ mask, float* __restrict__ X)
{
    extern __shared__ unsigned smu[];
    unsigned* Ks = smu;                       // [64][68]
    unsigned* Vs = smu + 64 * 68;             // [64][72]
    unsigned* Ps = Vs + 64 * 72;              // [64][68]
    float*    Cs = (float*)(Ps + 64 * 68);    // [64]
    float*    Ms = Cs + 64;                   // [64]

    const int tid  = threadIdx.x;
    const int lane = tid & 31, wq = tid >> 5;
    const int g = lane >> 2, t = lane & 3;    // quad group / thread-in-group
    const int q0 = wq << 4;                   // warp's first query row
    const int b = blockIdx.z, h = blockIdx.y;
    const int t0 = blockIdx.x << 6;

    // ---- preload Q tile (via Ks buffer) into A-fragments, tf32-rounded ----
    {
        const float* qb = Q + ((size_t)(b * Tc + t0)) * Dc + h * DKc;
#pragma unroll
        for (int i = 0; i < 8; i++) {
            int idx = tid + 128 * i;
            int row = idx >> 4, c4 = (idx & 15) << 2;
            float4 v4 = *(const float4*)(qb + (size_t)row * Dc + c4);
            *(uint4*)&Ks[row * 68 + c4] =
                make_uint4(cvt_tf32(v4.x), cvt_tf32(v4.y),
                           cvt_tf32(v4.z), cvt_tf32(v4.w));
        }
    }
    __syncthreads();
    unsigned qA[8][4];
#pragma unroll
    for (int jk = 0; jk < 8; jk++) {
        const int kk = jk << 3;
        qA[jk][0] = Ks[(q0 + g)     * 68 + kk + t];
        qA[jk][1] = Ks[(q0 + g + 8) * 68 + kk + t];
        qA[jk][2] = Ks[(q0 + g)     * 68 + kk + t + 4];
        qA[jk][3] = Ks[(q0 + g + 8) * 68 + kk + t + 4];
    }

    float m0r = -1e30f, m1r = -1e30f, l0 = 0.f, l1 = 0.f;
    float oacc[8][4];
#pragma unroll
    for (int jn = 0; jn < 8; jn++)
#pragma unroll
        for (int c = 0; c < 4; c++) oacc[jn][c] = 0.f;

    for (int s0 = 0; s0 < Tc; s0 += 64) {
        __syncthreads();   // previous iter (and Q-frag reads) done

        // ---- fill K and V tiles (tf32) + C bias + mask ----
        {
            const float* kb = Kp + ((size_t)(b * Tc + s0)) * Dc + h * DKc;
            const float* vb = V  + ((size_t)(b * Tc + s0)) * Dc + h * DKc;
#pragma unroll
            for (int i = 0; i < 8; i++) {
                int idx = tid + 128 * i;
                int row = idx >> 4, c4 = (idx & 15) << 2;
                float4 k4 = *(const float4*)(kb + (size_t)row * Dc + c4);
                *(uint4*)&Ks[row * 68 + c4] =
                    make_uint4(cvt_tf32(k4.x), cvt_tf32(k4.y),
                               cvt_tf32(k4.z), cvt_tf32(k4.w));
                float4 v4 = *(const float4*)(vb + (size_t)row * Dc + c4);
                *(uint4*)&Vs[row * 72 + c4] =
                    make_uint4(cvt_tf32(v4.x), cvt_tf32(v4.y),
                               cvt_tf32(v4.z), cvt_tf32(v4.w));
            }
            if (tid < 64) {
                Cs[tid] = C[((size_t)b * Hc + h) * Tc + s0 + tid];
                Ms[tid] = (float)mask[b * Tc + s0 + tid];
            }
        }
        __syncthreads();

        // ---- S = Q . Kp^T  (16 q x 64 s per warp) ----
        float sc[8][4];
#pragma unroll
        for (int jn = 0; jn < 8; jn++)
#pragma unroll
            for (int c = 0; c < 4; c++) sc[jn][c] = 0.f;

#pragma unroll
        for (int jk = 0; jk < 8; jk++) {
            const int kk = jk << 3;
#pragma unroll
            for (int jn = 0; jn < 8; jn++) {
                unsigned b0 = Ks[((jn << 3) + g) * 68 + kk + t];
                unsigned b1 = Ks[((jn << 3) + g) * 68 + kk + t + 4];
                mma_tf32(sc[jn][0], sc[jn][1], sc[jn][2], sc[jn][3],
                         qA[jk][0], qA[jk][1], qA[jk][2], qA[jk][3], b0, b1);
            }
        }

        // ---- bias + mask + scale; row maxes ----
        float pmax0 = -1e30f, pmax1 = -1e30f;
#pragma unroll
        for (int jn = 0; jn < 8; jn++) {
            const int n0 = (jn << 3) + (t << 1);
            float2 cb = *(const float2*)&Cs[n0];
            float2 mk = *(const float2*)&Ms[n0];
            sc[jn][0] = (mk.x != 0.f) ? (sc[jn][0] + cb.x) * 0.125f : -1e30f;
            sc[jn][1] = (mk.y != 0.f) ? (sc[jn][1] + cb.y) * 0.125f : -1e30f;
            sc[jn][2] = (mk.x != 0.f) ? (sc[jn][2] + cb.x) * 0.125f : -1e30f;
            sc[jn][3] = (mk.y != 0.f) ? (sc[jn][3] + cb.y) * 0.125f : -1e30f;
            pmax0 = fmaxf(pmax0, fmaxf(sc[jn][0], sc[jn][1]));
            pmax1 = fmaxf(pmax1, fmaxf(sc[jn][2], sc[jn][3]));
        }
        pmax0 = fmaxf(pmax0, __shfl_xor_sync(0xffffffffu, pmax0, 1));
        pmax0 = fmaxf(pmax0, __shfl_xor_sync(0xffffffffu, pmax0, 2));
        pmax1 = fmaxf(pmax1, __shfl_xor_sync(0xffffffffu, pmax1, 1));
        pmax1 = fmaxf(pmax1, __shfl_xor_sync(0xffffffffu, pmax1, 2));

        const float mn0 = fmaxf(m0r, pmax0), mn1 = fmaxf(m1r, pmax1);
        const float al0 = __expf(m0r - mn0), al1 = __expf(m1r - mn1);
        m0r = mn0; m1r = mn1;
#pragma unroll
        for (int jn = 0; jn < 8; jn++) {
            oacc[jn][0] *= al0; oacc[jn][1] *= al0;
            oacc[jn][2] *= al1; oacc[jn][3] *= al1;
        }

        // ---- exp, row sums, write P (tf32) to smem ----
        float rs0 = 0.f, rs1 = 0.f;
#pragma unroll
        for (int jn = 0; jn < 8; jn++) {
            const int n0 = (jn << 3) + (t << 1);
            float p00 = __expf(sc[jn][0] - mn0);
            float p01 = __expf(sc[jn][1] - mn0);
            float p10 = __expf(sc[jn][2] - mn1);
            float p11 = __expf(sc[jn][3] - mn1);
            rs0 += p00 + p01;
            rs1 += p10 + p11;
            *(uint2*)&Ps[(q0 + g)     * 68 + n0] = make_uint2(cvt_tf32(p00), cvt_tf32(p01));
            *(uint2*)&Ps[(q0 + g + 8) * 68 + n0] = make_uint2(cvt_tf32(p10), cvt_tf32(p11));
        }
        rs0 += __shfl_xor_sync(0xffffffffu, rs0, 1);
        rs0 += __shfl_xor_sync(0xffffffffu, rs0, 2);
        rs1 += __shfl_xor_sync(0xffffffffu, rs1, 1);
        rs1 += __shfl_xor_sync(0xffffffffu, rs1, 2);
        l0 = l0 * al0 + rs0;
        l1 = l1 * al1 + rs1;
        __syncwarp();      // Ps is warp-private (rows q0..q0+15)

        // ---- O += P @ V ----
#pragma unroll
        for (int jk = 0; jk < 8; jk++) {
            const int kk = jk << 3;
            unsigned pa0 = Ps[(q0 + g)     * 68 + kk + t];
            unsigned pa1 = Ps[(q0 + g + 8) * 68 + kk + t];
            unsigned pa2 = Ps[(q0 + g)     * 68 + kk + t + 4];
            unsigned pa3 = Ps[(q0 + g + 8) * 68 + kk + t + 4];
#pragma unroll
            for (int jn = 0; jn < 8; jn++) {
                unsigned b0 = Vs[(kk + t)     * 72 + (jn << 3) + g];
                unsigned b1 = Vs[(kk + t + 4) * 72 + (jn << 3) + g];
                mma_tf32(oacc[jn][0], oacc[jn][1], oacc[jn][2], oacc[jn][3],
                         pa0, pa1, pa2, pa3, b0, b1);
            }
        }
    }

    // ---- normalize & write; all-masked rows (m stuck at -1e30) -> 0 ----
    const float inv0 = (m0r > -1e29f) ? (1.f / l0) : 0.f;
    const float inv1 = (m1r > -1e29f) ? (1.f / l1) : 0.f;
    float* x0 = X + ((size_t)(b * Tc + t0 + q0 + g))     * Dc + h * DKc + (t << 1);
    float* x1 = X + ((size_t)(b * Tc + t0 + q0 + g + 8)) * Dc + h * DKc + (t << 1);
#pragma unroll
    for (int jn = 0; jn < 8; jn++) {
        *(float2*)(x0 + (jn << 3)) = make_float2(oacc[jn][0] * inv0, oacc[jn][1] * inv0);
        *(float2*)(x1 + (jn << 3)) = make_float2(oacc[jn][2] * inv1, oacc[jn][3] * inv1);
    }
}

// ---------------------------------------------------------------------------
extern "C" void kernel_launch(void* const* d_in, const int* in_sizes, int n_in,
                              void* d_out, int out_size)
{
    (void)in_sizes; (void)n_in; (void)out_size;
    const float* query = (const float*)d_in[0];
    const float* key   = (const float*)d_in[1];
    const float* value = (const float*)d_in[2];
    const int*   mask  = (const int*)  d_in[3];
    const float* pos   = (const float*)d_in[4];
    const float* Wq    = (const float*)d_in[5];
    const float* bq    = (const float*)d_in[6];
    const float* Wk    = (const float*)d_in[7];
    const float* bk    = (const float*)d_in[8];
    const float* Wv    = (const float*)d_in[9];
    const float* bv    = (const float*)d_in[10];
    const float* Wo    = (const float*)d_in[11];
    const float* bo    = (const float*)d_in[12];
    const float* Wp    = (const float*)d_in[13];
    const float* u     = (const float*)d_in[14];
    const float* v     = (const float*)d_in[15];
    float* out = (float*)d_out;

    float *Qb, *Kb, *Vb, *Pb, *Cb, *Xb;
    cudaGetSymbolAddress((void**)&Qb, g_Q);
    cudaGetSymbolAddress((void**)&Kb, g_K);
    cudaGetSymbolAddress((void**)&Vb, g_V);
    cudaGetSymbolAddress((void**)&Pb, g_P);
    cudaGetSymbolAddress((void**)&Cb, g_C);
    cudaGetSymbolAddress((void**)&Xb, g_X);

    cudaFuncSetAttribute(attn_kernel,
                         cudaFuncAttributeMaxDynamicSharedMemorySize,
                         ATTN_SMEM_BYTES);

    // P = pos_emb @ Wp^T (no bias)
    gemm_bias_kernel<<<dim3(Dc / 64, Tc / 64), 256>>>(pos, Wp, nullptr, Pb, Tc, Dc, Dc);
    // Q/K/V projections
    gemm_bias_kernel<<<dim3(Dc / 64, (Bc * Tc) / 64), 256>>>(query, Wq, bq, Qb, Bc * Tc, Dc, Dc);
    gemm_bias_kernel<<<dim3(Dc / 64, (Bc * Tc) / 64), 256>>>(key,   Wk, bk, Kb, Bc * Tc, Dc, Dc);
    gemm_bias_kernel<<<dim3(Dc / 64, (Bc * Tc) / 64), 256>>>(value, Wv, bv, Vb, Bc * Tc, Dc, Dc);
    // Kp = K + P (in place) and per-(b,h,s) bias C = u.k + v.p
    kp_c_kernel<<<Bc * Tc, Dc>>>(Kb, Pb, u, v, Cb);
    // Flash attention (TF32 tensor-core MMA)
    attn_kernel<<<dim3(Tc / 64, Hc, Bc), 128, ATTN_SMEM_BYTES>>>(Qb, Kb, Vb, Cb, mask, Xb);
    // Output projection
    gemm_bias_kernel<<<dim3(Dc / 64, (Bc * Tc) / 64), 256>>>(Xb, Wo, bo, out, Bc * Tc, Dc, Dc);
}

// round 15
// speedup vs baseline: 2.6266x; 1.1032x over previous
#include <cuda_runtime.h>
#include <cstddef>

// Problem constants (fixed by the dataset)
constexpr int Bc  = 4;
constexpr int Tc  = 2048;
constexpr int Dc  = 512;
constexpr int Hc  = 8;
constexpr int DKc = 64;   // Dc / Hc

// -------------------- scratch (device globals; no allocation allowed) ------
__device__ float g_Q[(size_t)Bc * Tc * Dc];
__device__ float g_K[(size_t)Bc * Tc * Dc];   // K proj, then Kp = K + P in-place
__device__ float g_V[(size_t)Bc * Tc * Dc];
__device__ float g_P[(size_t)Tc * Dc];
__device__ float g_C[(size_t)Bc * Hc * Tc];   // per-(b,h,s) bias  u.k + v.p
__device__ float g_X[(size_t)Bc * Tc * Dc];

// -------------------- tf32 helpers -----------------------------------------
__device__ __forceinline__ unsigned cvt_tf32(float f) {
    unsigned r; asm("cvt.rna.tf32.f32 %0, %1;" : "=r"(r) : "f"(f)); return r;
}
__device__ __forceinline__ void mma_tf32(
    float& c0, float& c1, float& c2, float& c3,
    unsigned a0, unsigned a1, unsigned a2, unsigned a3,
    unsigned b0, unsigned b1)
{
    asm("mma.sync.aligned.m16n8k8.row.col.f32.tf32.tf32.f32 "
        "{%0,%1,%2,%3}, {%4,%5,%6,%7}, {%8,%9}, {%0,%1,%2,%3};"
        : "+f"(c0), "+f"(c1), "+f"(c2), "+f"(c3)
        : "r"(a0), "r"(a1), "r"(a2), "r"(a3), "r"(b0), "r"(b1));
}

// ---------------------------------------------------------------------------
// 3xTF32 tensor-core GEMM: out[M,N] = A[M,K] @ W[N,K]^T (+ bias[N]).
// fp32-accurate via Markidis split: x = hi + lo (exact), acc += hi*hi + hi*lo
// + lo*hi. Block tile 128x128x32, 256 threads = 8 warps (2m x 4n), warp tile
// 64x32. hi/lo tiles converted once at fill time, stored [k][idx] stride 136
// (8t+g bank mapping -> conflict-free fragment loads).
// ---------------------------------------------------------------------------
constexpr int GS = 136;                        // smem k-row stride (words)
constexpr int GEMM_SMEM_WORDS = 4 * 32 * GS;   // Ah, Al, Wh, Wl
constexpr int GEMM_SMEM_BYTES = GEMM_SMEM_WORDS * 4;   // 69632

__global__ __launch_bounds__(256, 2) void gemm3t_kernel(
    const float* __restrict__ A, const float* __restrict__ W,
    const float* __restrict__ bias, float* __restrict__ out,
    int M, int N, int K)
{
    extern __shared__ unsigned smg[];
    unsigned* Ah = smg;
    unsigned* Al = Ah + 32 * GS;
    unsigned* Wh = Al + 32 * GS;
    unsigned* Wl = Wh + 32 * GS;

    const int tid  = threadIdx.x;
    const int lane = tid & 31, wid = tid >> 5;
    const int wm = wid & 1, wn = wid >> 1;     // warp tile: 64m x 32n
    const int g = lane >> 2, t = lane & 3;
    const int m0 = blockIdx.y << 7, n0 = blockIdx.x << 7;
    const int lr = tid & 127;                  // tile row handled by this thread
    const int lc = (tid >> 7) << 4;            // k offset: 0 or 16

    const float* Ap = A + (size_t)(m0 + lr) * K + lc;
    const float* Wp = W + (size_t)(n0 + lr) * K + lc;

    float acc[4][4][4];
#pragma unroll
    for (int im = 0; im < 4; im++)
#pragma unroll
        for (int jn = 0; jn < 4; jn++)
#pragma unroll
            for (int c = 0; c < 4; c++) acc[im][jn][c] = 0.f;

    for (int k0 = 0; k0 < K; k0 += 32) {
        float av[16], wv[16];
#pragma unroll
        for (int q = 0; q < 4; q++) {
            *(float4*)&av[q * 4] = *(const float4*)(Ap + k0 + q * 4);
            *(float4*)&wv[q * 4] = *(const float4*)(Wp + k0 + q * 4);
        }
        __syncthreads();    // previous stage's compute done before overwrite
#pragma unroll
        for (int q = 0; q < 16; q++) {
            unsigned ahi = cvt_tf32(av[q]);
            unsigned alo = cvt_tf32(av[q] - __uint_as_float(ahi));
            Ah[(lc + q) * GS + lr] = ahi;
            Al[(lc + q) * GS + lr] = alo;
            unsigned whi = cvt_tf32(wv[q]);
            unsigned wlo = cvt_tf32(wv[q] - __uint_as_float(whi));
            Wh[(lc + q) * GS + lr] = whi;
            Wl[(lc + q) * GS + lr] = wlo;
        }
        __syncthreads();

#pragma unroll
        for (int k8 = 0; k8 < 4; k8++) {
            const int kk = k8 << 3;
            // A fragments (hi+lo) for the warp's 4 m16 tiles
            unsigned ah[4][4], al[4][4];
#pragma unroll
            for (int im = 0; im < 4; im++) {
                const int r0 = (kk + t) * GS + (wm << 6) + (im << 4) + g;
                const int r1 = (kk + t + 4) * GS + (wm << 6) + (im << 4) + g;
                ah[im][0] = Ah[r0]; ah[im][1] = Ah[r0 + 8];
                ah[im][2] = Ah[r1]; ah[im][3] = Ah[r1 + 8];
                al[im][0] = Al[r0]; al[im][1] = Al[r0 + 8];
                al[im][2] = Al[r1]; al[im][3] = Al[r1 + 8];
            }
#pragma unroll
            for (int jn = 0; jn < 4; jn++) {
                const int b0i = (kk + t) * GS + (wn << 5) + (jn << 3) + g;
                const int b1i = (kk + t + 4) * GS + (wn << 5) + (jn << 3) + g;
                unsigned bh0 = Wh[b0i], bh1 = Wh[b1i];
                unsigned bl0 = Wl[b0i], bl1 = Wl[b1i];
#pragma unroll
                for (int im = 0; im < 4; im++)
                    mma_tf32(acc[im][jn][0], acc[im][jn][1], acc[im][jn][2], acc[im][jn][3],
                             ah[im][0], ah[im][1], ah[im][2], ah[im][3], bh0, bh1);
#pragma unroll
                for (int im = 0; im < 4; im++)
                    mma_tf32(acc[im][jn][0], acc[im][jn][1], acc[im][jn][2], acc[im][jn][3],
                             ah[im][0], ah[im][1], ah[im][2], ah[im][3], bl0, bl1);
#pragma unroll
                for (int im = 0; im < 4; im++)
                    mma_tf32(acc[im][jn][0], acc[im][jn][1], acc[im][jn][2], acc[im][jn][3],
                             al[im][0], al[im][1], al[im][2], al[im][3], bh0, bh1);
            }
        }
    }

    // epilogue: C rows g / g+8, cols 2t / 2t+1 within each (im, jn) tile
#pragma unroll
    for (int im = 0; im < 4; im++) {
        const int r0 = m0 + (wm << 6) + (im << 4) + g;
#pragma unroll
        for (int jn = 0; jn < 4; jn++) {
            const int cc = n0 + (wn << 5) + (jn << 3) + (t << 1);
            float b0 = bias ? bias[cc] : 0.f;
            float b1 = bias ? bias[cc + 1] : 0.f;
            *(float2*)(out + (size_t)r0 * N + cc) =
                make_float2(acc[im][jn][0] + b0, acc[im][jn][1] + b1);
            *(float2*)(out + (size_t)(r0 + 8) * N + cc) =
                make_float2(acc[im][jn][2] + b0, acc[im][jn][3] + b1);
        }
    }
}

// ---------------------------------------------------------------------------
// Fuse: Kp = K + P (in place), C[b,h,s] = sum_d u[h,d]*K + v[h,d]*P
// ---------------------------------------------------------------------------
__global__ __launch_bounds__(512) void kp_c_kernel(
    float* __restrict__ K, const float* __restrict__ P,
    const float* __restrict__ u, const float* __restrict__ v,
    float* __restrict__ C)
{
    __shared__ float prod[512];
    const int bs = blockIdx.x;
    const int s  = bs & (Tc - 1);
    const int d  = threadIdx.x;

    const size_t kidx = (size_t)bs * Dc + d;
    float kv = K[kidx];
    float pv = P[(size_t)s * Dc + d];
    K[kidx] = kv + pv;
    prod[d] = u[d] * kv + v[d] * pv;
    __syncthreads();
#pragma unroll
    for (int off = 32; off > 0; off >>= 1) {
        if ((d & 63) < off) prod[d] += prod[d + off];
        __syncthreads();
    }
    if ((d & 63) == 0) {
        const int b = bs >> 11;
        C[((size_t)b * Hc + (d >> 6)) * Tc + s] = prod[d];
    }
}

// ---------------------------------------------------------------------------
// Flash attention with mma.sync m16n8k8 TF32 (unchanged from R13, passing).
// Block = (b, h, 64-query tile), 128 threads (4 warps x 16 queries).
// ---------------------------------------------------------------------------
constexpr int ATTN_SMEM_WORDS = 64 * 68 + 64 * 72 + 64 * 68 + 64 + 64;
constexpr int ATTN_SMEM_BYTES = ATTN_SMEM_WORDS * 4;   // 53760

__global__ __launch_bounds__(128) void attn_kernel(
    const float* __restrict__ Q, const float* __restrict__ Kp,
    const float* __restrict__ V, const float* __restrict__ C,
    const int* __restrict__ mask, float* __restrict__ X)
{
    extern __shared__ unsigned smu[];
    unsigned* Ks = smu;                       // [64][68]
    unsigned* Vs = smu + 64 * 68;             // [64][72]
    unsigned* Ps = Vs + 64 * 72;              // [64][68]
    float*    Cs = (float*)(Ps + 64 * 68);    // [64]
    float*    Ms = Cs + 64;                   // [64]

    const int tid  = threadIdx.x;
    const int lane = tid & 31, wq = tid >> 5;
    const int g = lane >> 2, t = lane & 3;
    const int q0 = wq << 4;
    const int b = blockIdx.z, h = blockIdx.y;
    const int t0 = blockIdx.x << 6;

    // ---- preload Q tile (via Ks buffer) into A-fragments, tf32-rounded ----
    {
        const float* qb = Q + ((size_t)(b * Tc + t0)) * Dc + h * DKc;
#pragma unroll
        for (int i = 0; i < 8; i++) {
            int idx = tid + 128 * i;
            int row = idx >> 4, c4 = (idx & 15) << 2;
            float4 v4 = *(const float4*)(qb + (size_t)row * Dc + c4);
            *(uint4*)&Ks[row * 68 + c4] =
                make_uint4(cvt_tf32(v4.x), cvt_tf32(v4.y),
                           cvt_tf32(v4.z), cvt_tf32(v4.w));
        }
    }
    __syncthreads();
    unsigned qA[8][4];
#pragma unroll
    for (int jk = 0; jk < 8; jk++) {
        const int kk = jk << 3;
        qA[jk][0] = Ks[(q0 + g)     * 68 + kk + t];
        qA[jk][1] = Ks[(q0 + g + 8) * 68 + kk + t];
        qA[jk][2] = Ks[(q0 + g)     * 68 + kk + t + 4];
        qA[jk][3] = Ks[(q0 + g + 8) * 68 + kk + t + 4];
    }

    float m0r = -1e30f, m1r = -1e30f, l0 = 0.f, l1 = 0.f;
    float oacc[8][4];
#pragma unroll
    for (int jn = 0; jn < 8; jn++)
#pragma unroll
        for (int c = 0; c < 4; c++) oacc[jn][c] = 0.f;

    for (int s0 = 0; s0 < Tc; s0 += 64) {
        __syncthreads();

        {
            const float* kb = Kp + ((size_t)(b * Tc + s0)) * Dc + h * DKc;
            const float* vb = V  + ((size_t)(b * Tc + s0)) * Dc + h * DKc;
#pragma unroll
            for (int i = 0; i < 8; i++) {
                int idx = tid + 128 * i;
                int row = idx >> 4, c4 = (idx & 15) << 2;
                float4 k4 = *(const float4*)(kb + (size_t)row * Dc + c4);
                *(uint4*)&Ks[row * 68 + c4] =
                    make_uint4(cvt_tf32(k4.x), cvt_tf32(k4.y),
                               cvt_tf32(k4.z), cvt_tf32(k4.w));
                float4 v4 = *(const float4*)(vb + (size_t)row * Dc + c4);
                *(uint4*)&Vs[row * 72 + c4] =
                    make_uint4(cvt_tf32(v4.x), cvt_tf32(v4.y),
                               cvt_tf32(v4.z), cvt_tf32(v4.w));
            }
            if (tid < 64) {
                Cs[tid] = C[((size_t)b * Hc + h) * Tc + s0 + tid];
                Ms[tid] = (float)mask[b * Tc + s0 + tid];
            }
        }
        __syncthreads();

        float sc[8][4];
#pragma unroll
        for (int jn = 0; jn < 8; jn++)
#pragma unroll
            for (int c = 0; c < 4; c++) sc[jn][c] = 0.f;

#pragma unroll
        for (int jk = 0; jk < 8; jk++) {
            const int kk = jk << 3;
#pragma unroll
            for (int jn = 0; jn < 8; jn++) {
                unsigned b0 = Ks[((jn << 3) + g) * 68 + kk + t];
                unsigned b1 = Ks[((jn << 3) + g) * 68 + kk + t + 4];
                mma_tf32(sc[jn][0], sc[jn][1], sc[jn][2], sc[jn][3],
                         qA[jk][0], qA[jk][1], qA[jk][2], qA[jk][3], b0, b1);
            }
        }

        float pmax0 = -1e30f, pmax1 = -1e30f;
#pragma unroll
        for (int jn = 0; jn < 8; jn++) {
            const int n0 = (jn << 3) + (t << 1);
            float2 cb = *(const float2*)&Cs[n0];
            float2 mk = *(const float2*)&Ms[n0];
            sc[jn][0] = (mk.x != 0.f) ? (sc[jn][0] + cb.x) * 0.125f : -1e30f;
            sc[jn][1] = (mk.y != 0.f) ? (sc[jn][1] + cb.y) * 0.125f : -1e30f;
            sc[jn][2] = (mk.x != 0.f) ? (sc[jn][2] + cb.x) * 0.125f : -1e30f;
            sc[jn][3] = (mk.y != 0.f) ? (sc[jn][3] + cb.y) * 0.125f : -1e30f;
            pmax0 = fmaxf(pmax0, fmaxf(sc[jn][0], sc[jn][1]));
            pmax1 = fmaxf(pmax1, fmaxf(sc[jn][2], sc[jn][3]));
        }
        pmax0 = fmaxf(pmax0, __shfl_xor_sync(0xffffffffu, pmax0, 1));
        pmax0 = fmaxf(pmax0, __shfl_xor_sync(0xffffffffu, pmax0, 2));
        pmax1 = fmaxf(pmax1, __shfl_xor_sync(0xffffffffu, pmax1, 1));
        pmax1 = fmaxf(pmax1, __shfl_xor_sync(0xffffffffu, pmax1, 2));

        const float mn0 = fmaxf(m0r, pmax0), mn1 = fmaxf(m1r, pmax1);
        const float al0 = __expf(m0r - mn0), al1 = __expf(m1r - mn1);
        m0r = mn0; m1r = mn1;
#pragma unroll
        for (int jn = 0; jn < 8; jn++) {
            oacc[jn][0] *= al0; oacc[jn][1] *= al0;
            oacc[jn][2] *= al1; oacc[jn][3] *= al1;
        }

        float rs0 = 0.f, rs1 = 0.f;
#pragma unroll
        for (int jn = 0; jn < 8; jn++) {
            const int n0 = (jn << 3) + (t << 1);
            float p00 = __expf(sc[jn][0] - mn0);
            float p01 = __expf(sc[jn][1] - mn0);
            float p10 = __expf(sc[jn][2] - mn1);
            float p11 = __expf(sc[jn][3] - mn1);
            rs0 += p00 + p01;
            rs1 += p10 + p11;
            *(uint2*)&Ps[(q0 + g)     * 68 + n0] = make_uint2(cvt_tf32(p00), cvt_tf32(p01));
            *(uint2*)&Ps[(q0 + g + 8) * 68 + n0] = make_uint2(cvt_tf32(p10), cvt_tf32(p11));
        }
        rs0 += __shfl_xor_sync(0xffffffffu, rs0, 1);
        rs0 += __shfl_xor_sync(0xffffffffu, rs0, 2);
        rs1 += __shfl_xor_sync(0xffffffffu, rs1, 1);
        rs1 += __shfl_xor_sync(0xffffffffu, rs1, 2);
        l0 = l0 * al0 + rs0;
        l1 = l1 * al1 + rs1;
        __syncwarp();      // Ps is warp-private (rows q0..q0+15)

#pragma unroll
        for (int jk = 0; jk < 8; jk++) {
            const int kk = jk << 3;
            unsigned pa0 = Ps[(q0 + g)     * 68 + kk + t];
            unsigned pa1 = Ps[(q0 + g + 8) * 68 + kk + t];
            unsigned pa2 = Ps[(q0 + g)     * 68 + kk + t + 4];
            unsigned pa3 = Ps[(q0 + g + 8) * 68 + kk + t + 4];
#pragma unroll
            for (int jn = 0; jn < 8; jn++) {
                unsigned b0 = Vs[(kk + t)     * 72 + (jn << 3) + g];
                unsigned b1 = Vs[(kk + t + 4) * 72 + (jn << 3) + g];
                mma_tf32(oacc[jn][0], oacc[jn][1], oacc[jn][2], oacc[jn][3],
                         pa0, pa1, pa2, pa3, b0, b1);
            }
        }
    }

    const float inv0 = (m0r > -1e29f) ? (1.f / l0) : 0.f;
    const float inv1 = (m1r > -1e29f) ? (1.f / l1) : 0.f;
    float* x0 = X + ((size_t)(b * Tc + t0 + q0 + g))     * Dc + h * DKc + (t << 1);
    float* x1 = X + ((size_t)(b * Tc + t0 + q0 + g + 8)) * Dc + h * DKc + (t << 1);
#pragma unroll
    for (int jn = 0; jn < 8; jn++) {
        *(float2*)(x0 + (jn << 3)) = make_float2(oacc[jn][0] * inv0, oacc[jn][1] * inv0);
        *(float2*)(x1 + (jn << 3)) = make_float2(oacc[jn][2] * inv1, oacc[jn][3] * inv1);
    }
}

// ---------------------------------------------------------------------------
extern "C" void kernel_launch(void* const* d_in, const int* in_sizes, int n_in,
                              void* d_out, int out_size)
{
    (void)in_sizes; (void)n_in; (void)out_size;
    const float* query = (const float*)d_in[0];
    const float* key   = (const float*)d_in[1];
    const float* value = (const float*)d_in[2];
    const int*   mask  = (const int*)  d_in[3];
    const float* pos   = (const float*)d_in[4];
    const float* Wq    = (const float*)d_in[5];
    const float* bq    = (const float*)d_in[6];
    const float* Wk    = (const float*)d_in[7];
    const float* bk    = (const float*)d_in[8];
    const float* Wv    = (const float*)d_in[9];
    const float* bv    = (const float*)d_in[10];
    const float* Wo    = (const float*)d_in[11];
    const float* bo    = (const float*)d_in[12];
    const float* Wp    = (const float*)d_in[13];
    const float* u     = (const float*)d_in[14];
    const float* v     = (const float*)d_in[15];
    float* out = (float*)d_out;

    float *Qb, *Kb, *Vb, *Pb, *Cb, *Xb;
    cudaGetSymbolAddress((void**)&Qb, g_Q);
    cudaGetSymbolAddress((void**)&Kb, g_K);
    cudaGetSymbolAddress((void**)&Vb, g_V);
    cudaGetSymbolAddress((void**)&Pb, g_P);
    cudaGetSymbolAddress((void**)&Cb, g_C);
    cudaGetSymbolAddress((void**)&Xb, g_X);

    cudaFuncSetAttribute(gemm3t_kernel,
                         cudaFuncAttributeMaxDynamicSharedMemorySize,
                         GEMM_SMEM_BYTES);
    cudaFuncSetAttribute(attn_kernel,
                         cudaFuncAttributeMaxDynamicSharedMemorySize,
                         ATTN_SMEM_BYTES);

    // P = pos_emb @ Wp^T (no bias)
    gemm3t_kernel<<<dim3(Dc / 128, Tc / 128), 256, GEMM_SMEM_BYTES>>>(
        pos, Wp, nullptr, Pb, Tc, Dc, Dc);
    // Q/K/V projections
    gemm3t_kernel<<<dim3(Dc / 128, (Bc * Tc) / 128), 256, GEMM_SMEM_BYTES>>>(
        query, Wq, bq, Qb, Bc * Tc, Dc, Dc);
    gemm3t_kernel<<<dim3(Dc / 128, (Bc * Tc) / 128), 256, GEMM_SMEM_BYTES>>>(
        key, Wk, bk, Kb, Bc * Tc, Dc, Dc);
    gemm3t_kernel<<<dim3(Dc / 128, (Bc * Tc) / 128), 256, GEMM_SMEM_BYTES>>>(
        value, Wv, bv, Vb, Bc * Tc, Dc, Dc);
    // Kp = K + P (in place) and per-(b,h,s) bias C = u.k + v.p
    kp_c_kernel<<<Bc * Tc, Dc>>>(Kb, Pb, u, v, Cb);
    // Flash attention (TF32 tensor-core MMA)
    attn_kernel<<<dim3(Tc / 64, Hc, Bc), 128, ATTN_SMEM_BYTES>>>(Qb, Kb, Vb, Cb, mask, Xb);
    // Output projection
    gemm3t_kernel<<<dim3(Dc / 128, (Bc * Tc) / 128), 256, GEMM_SMEM_BYTES>>>(
        Xb, Wo, bo, out, Bc * Tc, Dc, Dc);
}

// round 17
// speedup vs baseline: 3.1520x; 1.2001x over previous
#include <cuda_runtime.h>
#include <cstddef>

// Problem constants (fixed by the dataset)
constexpr int Bc  = 4;
constexpr int Tc  = 2048;
constexpr int Dc  = 512;
constexpr int Hc  = 8;
constexpr int DKc = 64;   // Dc / Hc

// -------------------- scratch (device globals; no allocation allowed) ------
__device__ float g_Q[(size_t)Bc * Tc * Dc];
__device__ float g_K[(size_t)Bc * Tc * Dc];   // K proj, then Kp = K + P in-place
__device__ float g_V[(size_t)Bc * Tc * Dc];
__device__ float g_P[(size_t)Tc * Dc];
__device__ float g_C[(size_t)Bc * Hc * Tc];   // per-(b,h,s) bias  u.k + v.p
__device__ float g_X[(size_t)Bc * Tc * Dc];

// -------------------- tf32 helpers (attention) ------------------------------
__device__ __forceinline__ unsigned cvt_tf32(float f) {
    unsigned r; asm("cvt.rna.tf32.f32 %0, %1;" : "=r"(r) : "f"(f)); return r;
}
__device__ __forceinline__ void mma_tf32(
    float& c0, float& c1, float& c2, float& c3,
    unsigned a0, unsigned a1, unsigned a2, unsigned a3,
    unsigned b0, unsigned b1)
{
    asm("mma.sync.aligned.m16n8k8.row.col.f32.tf32.tf32.f32 "
        "{%0,%1,%2,%3}, {%4,%5,%6,%7}, {%8,%9}, {%0,%1,%2,%3};"
        : "+f"(c0), "+f"(c1), "+f"(c2), "+f"(c3)
        : "r"(a0), "r"(a1), "r"(a2), "r"(a3), "r"(b0), "r"(b1));
}

// -------------------- bf16 helpers (projection GEMMs) ----------------------
// pack two floats to bf16x2 (lo = a, hi = b), round-to-nearest
__device__ __forceinline__ unsigned cvt2_bf16(float a, float b) {
    unsigned r; asm("cvt.rn.bf16x2.f32 %0, %1, %2;" : "=r"(r) : "f"(b), "f"(a));
    return r;
}
__device__ __forceinline__ void mma_bf16(
    float& c0, float& c1, float& c2, float& c3,
    unsigned a0, unsigned a1, unsigned a2, unsigned a3,
    unsigned b0, unsigned b1)
{
    asm("mma.sync.aligned.m16n8k16.row.col.f32.bf16.bf16.f32 "
        "{%0,%1,%2,%3}, {%4,%5,%6,%7}, {%8,%9}, {%0,%1,%2,%3};"
        : "+f"(c0), "+f"(c1), "+f"(c2), "+f"(c3)
        : "r"(a0), "r"(a1), "r"(a2), "r"(a3), "r"(b0), "r"(b1));
}

// ---------------------------------------------------------------------------
// 3xBF16 tensor-core GEMM: out[M,N] = A[M,K] @ W[N,K]^T (+ bias[N]).
// fp32-accurate via split x = hi + lo (bf16 each); acc += hi*hi + hi*lo +
// lo*hi (residual lo*lo ~2^-17 relative, negligible). Block tile 128x128x32,
// 256 threads = 8 warps (2m x 4n), warp tile 64x32, mma m16n8k16.
// Smem: packed k-pairs [kpair][idx], word stride 136: stores are
// consecutive-lane, fragment loads hit banks (8t+g) -- both conflict-free.
// ---------------------------------------------------------------------------
constexpr int GSB = 136;                       // u32 word stride per kpair row
constexpr int GEMM_SMEM_WORDS = 4 * 16 * GSB;  // Ah, Al, Wh, Wl
constexpr int GEMM_SMEM_BYTES = GEMM_SMEM_WORDS * 4;   // 34816

__global__ __launch_bounds__(256, 2) void gemm3b_kernel(
    const float* __restrict__ A, const float* __restrict__ W,
    const float* __restrict__ bias, float* __restrict__ out,
    int M, int N, int K)
{
    extern __shared__ unsigned smg[];
    unsigned* Ah = smg;
    unsigned* Al = Ah + 16 * GSB;
    unsigned* Wh = Al + 16 * GSB;
    unsigned* Wl = Wh + 16 * GSB;

    const int tid  = threadIdx.x;
    const int lane = tid & 31, wid = tid >> 5;
    const int wm = wid & 1, wn = wid >> 1;     // warp tile: 64m x 32n
    const int g = lane >> 2, t = lane & 3;
    const int m0 = blockIdx.y << 7, n0 = blockIdx.x << 7;
    const int lr = tid & 127;                  // tile row handled by this thread
    const int lc = (tid >> 7) << 4;            // k offset: 0 or 16

    const float* Ap = A + (size_t)(m0 + lr) * K + lc;
    const float* Wp = W + (size_t)(n0 + lr) * K + lc;

    float acc[4][4][4];
#pragma unroll
    for (int im = 0; im < 4; im++)
#pragma unroll
        for (int jn = 0; jn < 4; jn++)
#pragma unroll
            for (int c = 0; c < 4; c++) acc[im][jn][c] = 0.f;

    for (int k0 = 0; k0 < K; k0 += 32) {
        float av[16], wv[16];
#pragma unroll
        for (int q = 0; q < 4; q++) {
            *(float4*)&av[q * 4] = *(const float4*)(Ap + k0 + q * 4);
            *(float4*)&wv[q * 4] = *(const float4*)(Wp + k0 + q * 4);
        }
        __syncthreads();    // previous stage's compute done before overwrite
#pragma unroll
        for (int q = 0; q < 8; q++) {
            const int wc = ((lc >> 1) + q) * GSB + lr;
            float ax = av[2 * q], ay = av[2 * q + 1];
            unsigned ahw = cvt2_bf16(ax, ay);
            unsigned alw = cvt2_bf16(ax - __uint_as_float(ahw << 16),
                                     ay - __uint_as_float(ahw & 0xffff0000u));
            Ah[wc] = ahw;
            Al[wc] = alw;
            float wx = wv[2 * q], wy = wv[2 * q + 1];
            unsigned whw = cvt2_bf16(wx, wy);
            unsigned wlw = cvt2_bf16(wx - __uint_as_float(whw << 16),
                                     wy - __uint_as_float(whw & 0xffff0000u));
            Wh[wc] = whw;
            Wl[wc] = wlw;
        }
        __syncthreads();

#pragma unroll
        for (int s = 0; s < 2; s++) {          // two k16 steps per k32 chunk
            const int kp = s << 3;
            unsigned ah[4][4], al[4][4];
#pragma unroll
            for (int im = 0; im < 4; im++) {
                const int m = (wm << 6) + (im << 4) + g;
                const int i0 = (kp + t) * GSB + m;
                const int i1 = (kp + t + 4) * GSB + m;
                ah[im][0] = Ah[i0]; ah[im][1] = Ah[i0 + 8];
                ah[im][2] = Ah[i1]; ah[im][3] = Ah[i1 + 8];
                al[im][0] = Al[i0]; al[im][1] = Al[i0 + 8];
                al[im][2] = Al[i1]; al[im][3] = Al[i1 + 8];
            }
#pragma unroll
            for (int jn = 0; jn < 4; jn++) {
                const int n = (wn << 5) + (jn << 3) + g;
                const int b0i = (kp + t) * GSB + n;
                const int b1i = (kp + t + 4) * GSB + n;
                unsigned bh0 = Wh[b0i], bh1 = Wh[b1i];
                unsigned bl0 = Wl[b0i], bl1 = Wl[b1i];
#pragma unroll
                for (int im = 0; im < 4; im++)
                    mma_bf16(acc[im][jn][0], acc[im][jn][1], acc[im][jn][2], acc[im][jn][3],
                             ah[im][0], ah[im][1], ah[im][2], ah[im][3], bh0, bh1);
#pragma unroll
                for (int im = 0; im < 4; im++)
                    mma_bf16(acc[im][jn][0], acc[im][jn][1], acc[im][jn][2], acc[im][jn][3],
                             ah[im][0], ah[im][1], ah[im][2], ah[im][3], bl0, bl1);
#pragma unroll
                for (int im = 0; im < 4; im++)
                    mma_bf16(acc[im][jn][0], acc[im][jn][1], acc[im][jn][2], acc[im][jn][3],
                             al[im][0], al[im][1], al[im][2], al[im][3], bh0, bh1);
            }
        }
    }

    // epilogue: C rows g / g+8, cols 2t / 2t+1 within each (im, jn) tile
#pragma unroll
    for (int im = 0; im < 4; im++) {
        const int r0 = m0 + (wm << 6) + (im << 4) + g;
#pragma unroll
        for (int jn = 0; jn < 4; jn++) {
            const int cc = n0 + (wn << 5) + (jn << 3) + (t << 1);
            float b0 = bias ? bias[cc] : 0.f;
            float b1 = bias ? bias[cc + 1] : 0.f;
            *(float2*)(out + (size_t)r0 * N + cc) =
                make_float2(acc[im][jn][0] + b0, acc[im][jn][1] + b1);
            *(float2*)(out + (size_t)(r0 + 8) * N + cc) =
                make_float2(acc[im][jn][2] + b0, acc[im][jn][3] + b1);
        }
    }
}

// ---------------------------------------------------------------------------
// Fuse: Kp = K + P (in place), C[b,h,s] = sum_d u[h,d]*K + v[h,d]*P
// ---------------------------------------------------------------------------
__global__ __launch_bounds__(512) void kp_c_kernel(
    float* __restrict__ K, const float* __restrict__ P,
    const float* __restrict__ u, const float* __restrict__ v,
    float* __restrict__ C)
{
    __shared__ float prod[512];
    const int bs = blockIdx.x;
    const int s  = bs & (Tc - 1);
    const int d  = threadIdx.x;

    const size_t kidx = (size_t)bs * Dc + d;
    float kv = K[kidx];
    float pv = P[(size_t)s * Dc + d];
    K[kidx] = kv + pv;
    prod[d] = u[d] * kv + v[d] * pv;
    __syncthreads();
#pragma unroll
    for (int off = 32; off > 0; off >>= 1) {
        if ((d & 63) < off) prod[d] += prod[d + off];
        __syncthreads();
    }
    if ((d & 63) == 0) {
        const int b = bs >> 11;
        C[((size_t)b * Hc + (d >> 6)) * Tc + s] = prod[d];
    }
}

// ---------------------------------------------------------------------------
// Flash attention with mma.sync m16n8k8 TF32 (unchanged, passing @ ~280us).
// Block = (b, h, 64-query tile), 128 threads (4 warps x 16 queries).
// ---------------------------------------------------------------------------
constexpr int ATTN_SMEM_WORDS = 64 * 68 + 64 * 72 + 64 * 68 + 64 + 64;
constexpr int ATTN_SMEM_BYTES = ATTN_SMEM_WORDS * 4;   // 53760

__global__ __launch_bounds__(128) void attn_kernel(
    const float* __restrict__ Q, const float* __restrict__ Kp,
    const float* __restrict__ V, const float* __restrict__ C,
    const int* __restrict__ mask, float* __restrict__ X)
{
    extern __shared__ unsigned smu[];
    unsigned* Ks = smu;                       // [64][68]
    unsigned* Vs = smu + 64 * 68;             // [64][72]
    unsigned* Ps = Vs + 64 * 72;              // [64][68]
    float*    Cs = (float*)(Ps + 64 * 68);    // [64]
    float*    Ms = Cs + 64;                   // [64]

    const int tid  = threadIdx.x;
    const int lane = tid & 31, wq = tid >> 5;
    const int g = lane >> 2, t = lane & 3;
    const int q0 = wq << 4;
    const int b = blockIdx.z, h = blockIdx.y;
    const int t0 = blockIdx.x << 6;

    // ---- preload Q tile (via Ks buffer) into A-fragments, tf32-rounded ----
    {
        const float* qb = Q + ((size_t)(b * Tc + t0)) * Dc + h * DKc;
#pragma unroll
        for (int i = 0; i < 8; i++) {
            int idx = tid + 128 * i;
            int row = idx >> 4, c4 = (idx & 15) << 2;
            float4 v4 = *(const float4*)(qb + (size_t)row * Dc + c4);
            *(uint4*)&Ks[row * 68 + c4] =
                make_uint4(cvt_tf32(v4.x), cvt_tf32(v4.y),
                           cvt_tf32(v4.z), cvt_tf32(v4.w));
        }
    }
    __syncthreads();
    unsigned qA[8][4];
#pragma unroll
    for (int jk = 0; jk < 8; jk++) {
        const int kk = jk << 3;
        qA[jk][0] = Ks[(q0 + g)     * 68 + kk + t];
        qA[jk][1] = Ks[(q0 + g + 8) * 68 + kk + t];
        qA[jk][2] = Ks[(q0 + g)     * 68 + kk + t + 4];
        qA[jk][3] = Ks[(q0 + g + 8) * 68 + kk + t + 4];
    }

    float m0r = -1e30f, m1r = -1e30f, l0 = 0.f, l1 = 0.f;
    float oacc[8][4];
#pragma unroll
    for (int jn = 0; jn < 8; jn++)
#pragma unroll
        for (int c = 0; c < 4; c++) oacc[jn][c] = 0.f;

    for (int s0 = 0; s0 < Tc; s0 += 64) {
        __syncthreads();

        {
            const float* kb = Kp + ((size_t)(b * Tc + s0)) * Dc + h * DKc;
            const float* vb = V  + ((size_t)(b * Tc + s0)) * Dc + h * DKc;
#pragma unroll
            for (int i = 0; i < 8; i++) {
                int idx = tid + 128 * i;
                int row = idx >> 4, c4 = (idx & 15) << 2;
                float4 k4 = *(const float4*)(kb + (size_t)row * Dc + c4);
                *(uint4*)&Ks[row * 68 + c4] =
                    make_uint4(cvt_tf32(k4.x), cvt_tf32(k4.y),
                               cvt_tf32(k4.z), cvt_tf32(k4.w));
                float4 v4 = *(const float4*)(vb + (size_t)row * Dc + c4);
                *(uint4*)&Vs[row * 72 + c4] =
                    make_uint4(cvt_tf32(v4.x), cvt_tf32(v4.y),
                               cvt_tf32(v4.z), cvt_tf32(v4.w));
            }
            if (tid < 64) {
                Cs[tid] = C[((size_t)b * Hc + h) * Tc + s0 + tid];
                Ms[tid] = (float)mask[b * Tc + s0 + tid];
            }
        }
        __syncthreads();

        float sc[8][4];
#pragma unroll
        for (int jn = 0; jn < 8; jn++)
#pragma unroll
            for (int c = 0; c < 4; c++) sc[jn][c] = 0.f;

#pragma unroll
        for (int jk = 0; jk < 8; jk++) {
            const int kk = jk << 3;
#pragma unroll
            for (int jn = 0; jn < 8; jn++) {
                unsigned b0 = Ks[((jn << 3) + g) * 68 + kk + t];
                unsigned b1 = Ks[((jn << 3) + g) * 68 + kk + t + 4];
                mma_tf32(sc[jn][0], sc[jn][1], sc[jn][2], sc[jn][3],
                         qA[jk][0], qA[jk][1], qA[jk][2], qA[jk][3], b0, b1);
            }
        }

        float pmax0 = -1e30f, pmax1 = -1e30f;
#pragma unroll
        for (int jn = 0; jn < 8; jn++) {
            const int n0 = (jn << 3) + (t << 1);
            float2 cb = *(const float2*)&Cs[n0];
            float2 mk = *(const float2*)&Ms[n0];
            sc[jn][0] = (mk.x != 0.f) ? (sc[jn][0] + cb.x) * 0.125f : -1e30f;
            sc[jn][1] = (mk.y != 0.f) ? (sc[jn][1] + cb.y) * 0.125f : -1e30f;
            sc[jn][2] = (mk.x != 0.f) ? (sc[jn][2] + cb.x) * 0.125f : -1e30f;
            sc[jn][3] = (mk.y != 0.f) ? (sc[jn][3] + cb.y) * 0.125f : -1e30f;
            pmax0 = fmaxf(pmax0, fmaxf(sc[jn][0], sc[jn][1]));
            pmax1 = fmaxf(pmax1, fmaxf(sc[jn][2], sc[jn][3]));
        }
        pmax0 = fmaxf(pmax0, __shfl_xor_sync(0xffffffffu, pmax0, 1));
        pmax0 = fmaxf(pmax0, __shfl_xor_sync(0xffffffffu, pmax0, 2));
        pmax1 = fmaxf(pmax1, __shfl_xor_sync(0xffffffffu, pmax1, 1));
        pmax1 = fmaxf(pmax1, __shfl_xor_sync(0xffffffffu, pmax1, 2));

        const float mn0 = fmaxf(m0r, pmax0), mn1 = fmaxf(m1r, pmax1);
        const float al0 = __expf(m0r - mn0), al1 = __expf(m1r - mn1);
        m0r = mn0; m1r = mn1;
#pragma unroll
        for (int jn = 0; jn < 8; jn++) {
            oacc[jn][0] *= al0; oacc[jn][1] *= al0;
            oacc[jn][2] *= al1; oacc[jn][3] *= al1;
        }

        float rs0 = 0.f, rs1 = 0.f;
#pragma unroll
        for (int jn = 0; jn < 8; jn++) {
            const int n0 = (jn << 3) + (t << 1);
            float p00 = __expf(sc[jn][0] - mn0);
            float p01 = __expf(sc[jn][1] - mn0);
            float p10 = __expf(sc[jn][2] - mn1);
            float p11 = __expf(sc[jn][3] - mn1);
            rs0 += p00 + p01;
            rs1 += p10 + p11;
            *(uint2*)&Ps[(q0 + g)     * 68 + n0] = make_uint2(cvt_tf32(p00), cvt_tf32(p01));
            *(uint2*)&Ps[(q0 + g + 8) * 68 + n0] = make_uint2(cvt_tf32(p10), cvt_tf32(p11));
        }
        rs0 += __shfl_xor_sync(0xffffffffu, rs0, 1);
        rs0 += __shfl_xor_sync(0xffffffffu, rs0, 2);
        rs1 += __shfl_xor_sync(0xffffffffu, rs1, 1);
        rs1 += __shfl_xor_sync(0xffffffffu, rs1, 2);
        l0 = l0 * al0 + rs0;
        l1 = l1 * al1 + rs1;
        __syncwarp();      // Ps is warp-private (rows q0..q0+15)

#pragma unroll
        for (int jk = 0; jk < 8; jk++) {
            const int kk = jk << 3;
            unsigned pa0 = Ps[(q0 + g)     * 68 + kk + t];
            unsigned pa1 = Ps[(q0 + g + 8) * 68 + kk + t];
            unsigned pa2 = Ps[(q0 + g)     * 68 + kk + t + 4];
            unsigned pa3 = Ps[(q0 + g + 8) * 68 + kk + t + 4];
#pragma unroll
            for (int jn = 0; jn < 8; jn++) {
                unsigned b0 = Vs[(kk + t)     * 72 + (jn << 3) + g];
                unsigned b1 = Vs[(kk + t + 4) * 72 + (jn << 3) + g];
                mma_tf32(oacc[jn][0], oacc[jn][1], oacc[jn][2], oacc[jn][3],
                         pa0, pa1, pa2, pa3, b0, b1);
            }
        }
    }

    const float inv0 = (m0r > -1e29f) ? (1.f / l0) : 0.f;
    const float inv1 = (m1r > -1e29f) ? (1.f / l1) : 0.f;
    float* x0 = X + ((size_t)(b * Tc + t0 + q0 + g))     * Dc + h * DKc + (t << 1);
    float* x1 = X + ((size_t)(b * Tc + t0 + q0 + g + 8)) * Dc + h * DKc + (t << 1);
#pragma unroll
    for (int jn = 0; jn < 8; jn++) {
        *(float2*)(x0 + (jn << 3)) = make_float2(oacc[jn][0] * inv0, oacc[jn][1] * inv0);
        *(float2*)(x1 + (jn << 3)) = make_float2(oacc[jn][2] * inv1, oacc[jn][3] * inv1);
    }
}

// ---------------------------------------------------------------------------
extern "C" void kernel_launch(void* const* d_in, const int* in_sizes, int n_in,
                              void* d_out, int out_size)
{
    (void)in_sizes; (void)n_in; (void)out_size;
    const float* query = (const float*)d_in[0];
    const float* key   = (const float*)d_in[1];
    const float* value = (const float*)d_in[2];
    const int*   mask  = (const int*)  d_in[3];
    const float* pos   = (const float*)d_in[4];
    const float* Wq    = (const float*)d_in[5];
    const float* bq    = (const float*)d_in[6];
    const float* Wk    = (const float*)d_in[7];
    const float* bk    = (const float*)d_in[8];
    const float* Wv    = (const float*)d_in[9];
    const float* bv    = (const float*)d_in[10];
    const float* Wo    = (const float*)d_in[11];
    const float* bo    = (const float*)d_in[12];
    const float* Wp    = (const float*)d_in[13];
    const float* u     = (const float*)d_in[14];
    const float* v     = (const float*)d_in[15];
    float* out = (float*)d_out;

    float *Qb, *Kb, *Vb, *Pb, *Cb, *Xb;
    cudaGetSymbolAddress((void**)&Qb, g_Q);
    cudaGetSymbolAddress((void**)&Kb, g_K);
    cudaGetSymbolAddress((void**)&Vb, g_V);
    cudaGetSymbolAddress((void**)&Pb, g_P);
    cudaGetSymbolAddress((void**)&Cb, g_C);
    cudaGetSymbolAddress((void**)&Xb, g_X);

    cudaFuncSetAttribute(gemm3b_kernel,
                         cudaFuncAttributeMaxDynamicSharedMemorySize,
                         GEMM_SMEM_BYTES);
    cudaFuncSetAttribute(attn_kernel,
                         cudaFuncAttributeMaxDynamicSharedMemorySize,
                         ATTN_SMEM_BYTES);

    // P = pos_emb @ Wp^T (no bias)
    gemm3b_kernel<<<dim3(Dc / 128, Tc / 128), 256, GEMM_SMEM_BYTES>>>(
        pos, Wp, nullptr, Pb, Tc, Dc, Dc);
    // Q/K/V projections
    gemm3b_kernel<<<dim3(Dc / 128, (Bc * Tc) / 128), 256, GEMM_SMEM_BYTES>>>(
        query, Wq, bq, Qb, Bc * Tc, Dc, Dc);
    gemm3b_kernel<<<dim3(Dc / 128, (Bc * Tc) / 128), 256, GEMM_SMEM_BYTES>>>(
        key, Wk, bk, Kb, Bc * Tc, Dc, Dc);
    gemm3b_kernel<<<dim3(Dc / 128, (Bc * Tc) / 128), 256, GEMM_SMEM_BYTES>>>(
        value, Wv, bv, Vb, Bc * Tc, Dc, Dc);
    // Kp = K + P (in place) and per-(b,h,s) bias C = u.k + v.p
    kp_c_kernel<<<Bc * Tc, Dc>>>(Kb, Pb, u, v, Cb);
    // Flash attention (TF32 tensor-core MMA)
    attn_kernel<<<dim3(Tc / 64, Hc, Bc), 128, ATTN_SMEM_BYTES>>>(Qb, Kb, Vb, Cb, mask, Xb);
    // Output projection
    gemm3b_kernel<<<dim3(Dc / 128, (Bc * Tc) / 128), 256, GEMM_SMEM_BYTES>>>(
        Xb, Wo, bo, out, Bc * Tc, Dc, Dc);
}